// round 15
// baseline (speedup 1.0000x reference)
#include <cuda_runtime.h>
#include <cuda_fp16.h>
#include <math.h>
#include <stdint.h>

#define D_MODEL 1024
#define SEQ     2048
#define BATCH   2
#define NROWS   (BATCH*SEQ)   /* 4096 */
#define NHEAD   16
#define HD      64
#define FFDIM   4096
#define LN_EPS  1e-5f

/* ------------------- scratch (no allocations allowed) ------------------- */
__device__ float g_q  [NROWS*(size_t)D_MODEL];
__device__ float g_k  [NROWS*(size_t)D_MODEL];
__device__ float g_v  [NROWS*(size_t)D_MODEL];
__device__ float g_x2 [NROWS*(size_t)D_MODEL];
__device__ __half g_h_hi  [NROWS*(size_t)D_MODEL];
__device__ __half g_h_lo  [NROWS*(size_t)D_MODEL];
__device__ __half g_ctx_hi[NROWS*(size_t)D_MODEL];
__device__ __half g_ctx_lo[NROWS*(size_t)D_MODEL];
__device__ __half g_h2_hi [NROWS*(size_t)D_MODEL];
__device__ __half g_h2_lo [NROWS*(size_t)D_MODEL];
__device__ __half g_ff_hi [NROWS*(size_t)FFDIM];
__device__ __half g_ff_lo [NROWS*(size_t)FFDIM];
__device__ __half g_wq_hi[D_MODEL*(size_t)D_MODEL];
__device__ __half g_wq_lo[D_MODEL*(size_t)D_MODEL];
__device__ __half g_wk_hi[D_MODEL*(size_t)D_MODEL];
__device__ __half g_wk_lo[D_MODEL*(size_t)D_MODEL];
__device__ __half g_wv_hi[D_MODEL*(size_t)D_MODEL];
__device__ __half g_wv_lo[D_MODEL*(size_t)D_MODEL];
__device__ __half g_wo_hi[D_MODEL*(size_t)D_MODEL];
__device__ __half g_wo_lo[D_MODEL*(size_t)D_MODEL];
__device__ __half g_w1_hi[D_MODEL*(size_t)FFDIM];
__device__ __half g_w1_lo[D_MODEL*(size_t)FFDIM];
__device__ __half g_w2_hi[FFDIM*(size_t)D_MODEL];
__device__ __half g_w2_lo[FFDIM*(size_t)D_MODEL];

/* ============================ PTX helpers ============================ */
__device__ __forceinline__ uint32_t smem_u32(const void* p) {
    uint32_t a;
    asm("{ .reg .u64 t; cvta.to.shared.u64 t, %1; cvt.u32.u64 %0, t; }"
        : "=r"(a) : "l"(p));
    return a;
}
__device__ __forceinline__ void ldsm4(uint32_t r[4], uint32_t addr) {
    asm volatile("ldmatrix.sync.aligned.m8n8.x4.shared.b16 {%0,%1,%2,%3}, [%4];"
        : "=r"(r[0]), "=r"(r[1]), "=r"(r[2]), "=r"(r[3]) : "r"(addr));
}
__device__ __forceinline__ void ldsm4t(uint32_t r[4], uint32_t addr) {
    asm volatile("ldmatrix.sync.aligned.m8n8.x4.trans.shared.b16 {%0,%1,%2,%3}, [%4];"
        : "=r"(r[0]), "=r"(r[1]), "=r"(r[2]), "=r"(r[3]) : "r"(addr));
}
__device__ __forceinline__ void mma_f16(float d[4], const uint32_t a[4],
                                        const uint32_t b[2]) {
    asm volatile(
        "mma.sync.aligned.m16n8k16.row.col.f32.f16.f16.f32 "
        "{%0,%1,%2,%3}, {%4,%5,%6,%7}, {%8,%9}, {%0,%1,%2,%3};"
        : "+f"(d[0]), "+f"(d[1]), "+f"(d[2]), "+f"(d[3])
        : "r"(a[0]), "r"(a[1]), "r"(a[2]), "r"(a[3]), "r"(b[0]), "r"(b[1]));
}
__device__ __forceinline__ void cpa16(uint32_t dst, const void* src) {
    asm volatile("cp.async.cg.shared.global [%0], [%1], 16;"
                 :: "r"(dst), "l"(src) : "memory");
}
#define CP_COMMIT() asm volatile("cp.async.commit_group;" ::: "memory")
#define CP_WAIT(n)  asm volatile("cp.async.wait_group %0;" :: "n"(n) : "memory")

/* fp32 pair -> packed (hi half2, lo half2) */
__device__ __forceinline__ void split_h2(float x, float y, half2& hi, half2& lo) {
    __half hx = __float2half_rn(x), hy = __float2half_rn(y);
    hi = __halves2half2(hx, hy);
    lo = __floats2half2_rn(x - __half2float(hx), y - __half2float(hy));
}

/* ------------- fused weight fp32 -> hi/lo convert (6 arrays) ------------ */
#define DD4 (D_MODEL*D_MODEL/4)   /* 262144 -> 1024 blocks */
#define DF4 (D_MODEL*FFDIM/4)     /* 1048576 -> 4096 blocks */
__global__ __launch_bounds__(256) void cvt6_kernel(
    const float* __restrict__ wq, const float* __restrict__ wk,
    const float* __restrict__ wv, const float* __restrict__ wo,
    const float* __restrict__ w1, const float* __restrict__ w2,
    __half* qh, __half* ql, __half* kh, __half* kl, __half* vh, __half* vl,
    __half* oh, __half* ol, __half* h1p, __half* l1p, __half* h2p, __half* l2p)
{
    const int b = blockIdx.x;
    const float* in; __half* hi; __half* lo; int off;
    if      (b < 1024) { in = wq; hi = qh;  lo = ql;  off = b; }
    else if (b < 2048) { in = wk; hi = kh;  lo = kl;  off = b - 1024; }
    else if (b < 3072) { in = wv; hi = vh;  lo = vl;  off = b - 2048; }
    else if (b < 4096) { in = wo; hi = oh;  lo = ol;  off = b - 3072; }
    else if (b < 8192) { in = w1; hi = h1p; lo = l1p; off = b - 4096; }
    else               { in = w2; hi = h2p; lo = l2p; off = b - 8192; }
    const int i = off * 256 + threadIdx.x;
    const float4 v = ((const float4*)in)[i];
    half2 h01, l01, h23, l23;
    split_h2(v.x, v.y, h01, l01);
    split_h2(v.z, v.w, h23, l23);
    ((uint2*)hi)[i] = make_uint2(*(uint32_t*)&h01, *(uint32_t*)&h23);
    ((uint2*)lo)[i] = make_uint2(*(uint32_t*)&l01, *(uint32_t*)&l23);
}

/* --------------------- LayerNorm -> hi/lo fp16 out ---------------------- */
__global__ __launch_bounds__(256) void ln_kernel(
    const float* __restrict__ x, const float* __restrict__ alpha,
    const float* __restrict__ shift, __half* __restrict__ out_hi,
    __half* __restrict__ out_lo)
{
    const int row = blockIdx.x;
    const int tid = threadIdx.x;
    const float4 v = ((const float4*)(x + (size_t)row * D_MODEL))[tid];

    float s  = v.x + v.y + v.z + v.w;
    float ss = v.x*v.x + v.y*v.y + v.z*v.z + v.w*v.w;
    #pragma unroll
    for (int o = 16; o; o >>= 1) {
        s  += __shfl_xor_sync(0xffffffffu, s,  o);
        ss += __shfl_xor_sync(0xffffffffu, ss, o);
    }
    __shared__ float sm_s[8], sm_ss[8], sm_mean, sm_rstd;
    const int w = tid >> 5, lane = tid & 31;
    if (lane == 0) { sm_s[w] = s; sm_ss[w] = ss; }
    __syncthreads();
    if (w == 0) {
        float a = (lane < 8) ? sm_s[lane]  : 0.f;
        float b = (lane < 8) ? sm_ss[lane] : 0.f;
        #pragma unroll
        for (int o = 4; o; o >>= 1) {
            a += __shfl_xor_sync(0xffffffffu, a, o);
            b += __shfl_xor_sync(0xffffffffu, b, o);
        }
        if (lane == 0) {
            float mean = a * (1.f / D_MODEL);
            float var  = b * (1.f / D_MODEL) - mean * mean;
            sm_mean = mean;
            sm_rstd = rsqrtf(var + LN_EPS);
        }
    }
    __syncthreads();
    const float mean = sm_mean, rstd = sm_rstd;
    const float4 av = ((const float4*)alpha)[tid];
    const float4 sv = ((const float4*)shift)[tid];
    float4 ov;
    ov.x = av.x * (v.x - mean) * rstd + sv.x;
    ov.y = av.y * (v.y - mean) * rstd + sv.y;
    ov.z = av.z * (v.z - mean) * rstd + sv.z;
    ov.w = av.w * (v.w - mean) * rstd + sv.w;
    half2 h01, l01, h23, l23;
    split_h2(ov.x, ov.y, h01, l01);
    split_h2(ov.z, ov.w, h23, l23);
    ((uint2*)(out_hi + (size_t)row * D_MODEL))[tid] =
        make_uint2(*(uint32_t*)&h01, *(uint32_t*)&h23);
    ((uint2*)(out_lo + (size_t)row * D_MODEL))[tid] =
        make_uint2(*(uint32_t*)&l01, *(uint32_t*)&l23);
}

/* == mma.sync fp16-split GEMM, 128x128, BK=32, 2-stage, 2 CTAs/SM ======= */
enum { EPI_NONE = 0, EPI_BIAS_RES = 1, EPI_BIAS_GELU = 2 };

__device__ __forceinline__ float gelu_f(float x) {
    float t = tanhf(0.7978845608028654f * (x + 0.044715f * x * x * x));
    return 0.5f * x * (1.f + t);
}

#define BM 128
#define BN 128
#define BK 32
#define TC_THREADS 256
#define STAGES 2

/* per-stage smem layout (bytes):
   A_hi [128 x 80B] @0 ; A_lo @10240 ; B_hi [32 x 272B] @20480 ; B_lo @29184 */
#define A_PITCH   80
#define B_PITCH   272
#define A_LO_OFF  10240
#define B_HI_OFF  20480
#define B_LO_OFF  29184
#define STAGE_B   37888
#define GEMM_SMEM (STAGES*STAGE_B)   /* 75776 -> 2 CTAs/SM */

__device__ __forceinline__ void issue_stage(
    uint32_t st, const __half* __restrict__ Ah, const __half* __restrict__ Al,
    const __half* __restrict__ Bh, const __half* __restrict__ Bl,
    int row0, int col0, int k0, int K, int N, int tid)
{
    #pragma unroll
    for (int i = 0; i < 2; ++i) {
        const int ch = tid + i * TC_THREADS;
        const int r = ch >> 2, qa = ch & 3;
        const size_t ao = (size_t)(row0 + r) * K + k0 + qa * 8;
        cpa16(st + r * A_PITCH + qa * 16,            Ah + ao);
        cpa16(st + A_LO_OFF + r * A_PITCH + qa * 16, Al + ao);
        const int k = ch >> 4, qb = ch & 15;
        const size_t bo = (size_t)(k0 + k) * N + col0 + qb * 8;
        cpa16(st + B_HI_OFF + k * B_PITCH + qb * 16, Bh + bo);
        cpa16(st + B_LO_OFF + k * B_PITCH + qb * 16, Bl + bo);
    }
}

template<int EPI>
__global__ __launch_bounds__(TC_THREADS, 2) void gemm_tc(
    const __half* __restrict__ Ah, const __half* __restrict__ Al,
    const __half* __restrict__ Bh, const __half* __restrict__ Bl,
    const float* __restrict__ bias, const float* __restrict__ res,
    float* __restrict__ Cf, __half* __restrict__ Ch, __half* __restrict__ Cl,
    int M, int N, int K)
{
    extern __shared__ char smc[];
    const uint32_t sb = smem_u32(smc);
    const int tid  = threadIdx.x;
    const int wid  = tid >> 5, lane = tid & 31;
    const int warp_m = wid & 3, warp_n = wid >> 2;
    const int row0 = blockIdx.y * BM, col0 = blockIdx.x * BN;

    const uint32_t a_rel = (uint32_t)((warp_m * 32 + (lane & 15)) * A_PITCH
                                      + ((lane >> 4) << 4));
    const uint32_t b_rel = (uint32_t)(B_HI_OFF + (lane & 15) * B_PITCH
                                      + warp_n * 128 + ((lane >> 4) << 4));

    float acc[2][8][4];
    #pragma unroll
    for (int mt = 0; mt < 2; ++mt)
        #pragma unroll
        for (int nt = 0; nt < 8; ++nt)
            #pragma unroll
            for (int r = 0; r < 4; ++r) acc[mt][nt][r] = 0.f;

    const int nc = K / BK;

    issue_stage(sb, Ah, Al, Bh, Bl, row0, col0, 0, K, N, tid);
    CP_COMMIT();

    for (int c = 0; c < nc; ++c) {
        /* trailing sync of previous iter guarantees buffer (c+1)&1 is free */
        if (c + 1 < nc) {
            issue_stage(sb + ((c + 1) & 1) * STAGE_B,
                        Ah, Al, Bh, Bl, row0, col0, (c + 1) * BK, K, N, tid);
            CP_COMMIT();
        }
        CP_WAIT(1);          /* stage c landed (only stage c+1 in flight) */
        __syncthreads();

        const uint32_t st = sb + (uint32_t)((c & 1) * STAGE_B);
        #pragma unroll
        for (int ks = 0; ks < 2; ++ks) {
            uint32_t ah[2][4], al[2][4];
            #pragma unroll
            for (int mt = 0; mt < 2; ++mt) {
                ldsm4(ah[mt], st + a_rel + mt * (16*A_PITCH) + ks * 32);
                ldsm4(al[mt], st + a_rel + A_LO_OFF + mt * (16*A_PITCH) + ks * 32);
            }
            #pragma unroll
            for (int n2 = 0; n2 < 4; ++n2) {
                uint32_t th[4], tl[4];
                ldsm4t(th, st + b_rel + ks * (16*B_PITCH) + n2 * 32);
                ldsm4t(tl, st + b_rel + (B_LO_OFF-B_HI_OFF) + ks * (16*B_PITCH) + n2 * 32);
                #pragma unroll
                for (int mt = 0; mt < 2; ++mt) {
                    mma_f16(acc[mt][2*n2],   ah[mt], th);
                    mma_f16(acc[mt][2*n2],   ah[mt], tl);
                    mma_f16(acc[mt][2*n2],   al[mt], th);
                    mma_f16(acc[mt][2*n2+1], ah[mt], th + 2);
                    mma_f16(acc[mt][2*n2+1], ah[mt], tl + 2);
                    mma_f16(acc[mt][2*n2+1], al[mt], th + 2);
                }
            }
        }
        __syncthreads();     /* all warps done reading stage c */
    }

    /* epilogue */
    const int g = lane >> 2, t = lane & 3;
    #pragma unroll
    for (int mt = 0; mt < 2; ++mt) {
        #pragma unroll
        for (int nt = 0; nt < 8; ++nt) {
            const int r  = row0 + warp_m * 32 + mt * 16 + g;
            const int cx = col0 + warp_n * 64 + nt * 8 + t * 2;
            float2 v0 = make_float2(acc[mt][nt][0], acc[mt][nt][1]);
            float2 v1 = make_float2(acc[mt][nt][2], acc[mt][nt][3]);
            if (EPI == EPI_BIAS_RES) {
                const float2 bi = *(const float2*)(bias + cx);
                const float2 r0 = *(const float2*)(res + (size_t)r * N + cx);
                const float2 r1 = *(const float2*)(res + (size_t)(r + 8) * N + cx);
                v0.x += bi.x + r0.x; v0.y += bi.y + r0.y;
                v1.x += bi.x + r1.x; v1.y += bi.y + r1.y;
            }
            if (EPI == EPI_BIAS_GELU) {
                const float2 bi = *(const float2*)(bias + cx);
                v0.x = gelu_f(v0.x + bi.x); v0.y = gelu_f(v0.y + bi.y);
                v1.x = gelu_f(v1.x + bi.x); v1.y = gelu_f(v1.y + bi.y);
                half2 h0, l0, h1, l1;
                split_h2(v0.x, v0.y, h0, l0);
                split_h2(v1.x, v1.y, h1, l1);
                *(half2*)(Ch + (size_t)r * N + cx)       = h0;
                *(half2*)(Cl + (size_t)r * N + cx)       = l0;
                *(half2*)(Ch + (size_t)(r + 8) * N + cx) = h1;
                *(half2*)(Cl + (size_t)(r + 8) * N + cx) = l1;
            } else {
                *(float2*)(Cf + (size_t)r * N + cx)       = v0;
                *(float2*)(Cf + (size_t)(r + 8) * N + cx) = v1;
            }
        }
    }
}

/* ------------------- Flash attention (fp32, hi/lo out) ------------------ */
#define FLD 68

__global__ __launch_bounds__(256) void flash_kernel(
    const float* __restrict__ Q, const float* __restrict__ K,
    const float* __restrict__ V, __half* __restrict__ O_hi,
    __half* __restrict__ O_lo)
{
    extern __shared__ float sm[];
    float* QT = sm;
    float* KT = sm + 64 * FLD;
    float* VS = sm + 2 * 64 * FLD;

    const int tid = threadIdx.x;
    const int tx = tid & 15, ty = tid >> 4;
    const int q0 = blockIdx.x * 64;
    const int h = blockIdx.y, b = blockIdx.z;
    const size_t base = ((size_t)b * SEQ) * D_MODEL + (size_t)h * HD;

    const int lr  = tid >> 2;
    const int ld0 = (tid & 3) * 4;

    #pragma unroll
    for (int it = 0; it < 4; ++it) {
        const int d = ld0 + it * 16;
        float4 qv = *(const float4*)(Q + base + (size_t)(q0 + lr) * D_MODEL + d);
        QT[(d + 0) * FLD + lr] = qv.x;
        QT[(d + 1) * FLD + lr] = qv.y;
        QT[(d + 2) * FLD + lr] = qv.z;
        QT[(d + 3) * FLD + lr] = qv.w;
    }

    float m[4], l[4], o[4][4];
    #pragma unroll
    for (int i = 0; i < 4; i++) {
        m[i] = -INFINITY; l[i] = 0.f;
        #pragma unroll
        for (int j = 0; j < 4; j++) o[i][j] = 0.f;
    }

    const int ntiles = blockIdx.x + 1;
    for (int t = 0; t < ntiles; ++t) {
        const int k0 = t * 64;
        __syncthreads();
        #pragma unroll
        for (int it = 0; it < 4; ++it) {
            const int d = ld0 + it * 16;
            float4 kv = *(const float4*)(K + base + (size_t)(k0 + lr) * D_MODEL + d);
            KT[(d + 0) * FLD + lr] = kv.x;
            KT[(d + 1) * FLD + lr] = kv.y;
            KT[(d + 2) * FLD + lr] = kv.z;
            KT[(d + 3) * FLD + lr] = kv.w;
            float4 vv = *(const float4*)(V + base + (size_t)(k0 + lr) * D_MODEL + d);
            *(float4*)&VS[lr * FLD + d] = vv;
        }
        __syncthreads();

        float s[4][4];
        #pragma unroll
        for (int i = 0; i < 4; i++)
            #pragma unroll
            for (int j = 0; j < 4; j++) s[i][j] = 0.f;
        #pragma unroll 8
        for (int k = 0; k < 64; ++k) {
            float4 ra = *(const float4*)&QT[k * FLD + ty * 4];
            float4 rb = *(const float4*)&KT[k * FLD + tx * 4];
            float fa[4] = {ra.x, ra.y, ra.z, ra.w};
            float fb[4] = {rb.x, rb.y, rb.z, rb.w};
            #pragma unroll
            for (int i = 0; i < 4; i++)
                #pragma unroll
                for (int j = 0; j < 4; j++)
                    s[i][j] += fa[i] * fb[j];
        }
        const bool diag = (k0 == q0);
        #pragma unroll
        for (int i = 0; i < 4; i++)
            #pragma unroll
            for (int j = 0; j < 4; j++) {
                s[i][j] *= 0.125f;
                if (diag && (tx * 4 + j > ty * 4 + i)) s[i][j] = -INFINITY;
            }

        float pv[4][4];
        #pragma unroll
        for (int i = 0; i < 4; i++) {
            float rm = fmaxf(fmaxf(s[i][0], s[i][1]), fmaxf(s[i][2], s[i][3]));
            #pragma unroll
            for (int off = 1; off < 16; off <<= 1)
                rm = fmaxf(rm, __shfl_xor_sync(0xffffffffu, rm, off));
            const float nm = fmaxf(m[i], rm);
            const float alpha = __expf(m[i] - nm);
            m[i] = nm;
            float rs = 0.f;
            #pragma unroll
            for (int j = 0; j < 4; j++) {
                pv[i][j] = __expf(s[i][j] - nm);
                rs += pv[i][j];
            }
            #pragma unroll
            for (int off = 1; off < 16; off <<= 1)
                rs += __shfl_xor_sync(0xffffffffu, rs, off);
            l[i] = l[i] * alpha + rs;
            #pragma unroll
            for (int j = 0; j < 4; j++) o[i][j] *= alpha;
        }

        __syncthreads();
        #pragma unroll
        for (int i = 0; i < 4; i++)
            #pragma unroll
            for (int j = 0; j < 4; j++)
                KT[(tx * 4 + j) * FLD + ty * 4 + i] = pv[i][j];
        __syncthreads();

        #pragma unroll 8
        for (int kk = 0; kk < 64; ++kk) {
            float4 rp = *(const float4*)&KT[kk * FLD + ty * 4];
            float4 rv = *(const float4*)&VS[kk * FLD + tx * 4];
            float fp[4] = {rp.x, rp.y, rp.z, rp.w};
            float fv[4] = {rv.x, rv.y, rv.z, rv.w};
            #pragma unroll
            for (int i = 0; i < 4; i++)
                #pragma unroll
                for (int j = 0; j < 4; j++)
                    o[i][j] += fp[i] * fv[j];
        }
    }

    #pragma unroll
    for (int i = 0; i < 4; i++) {
        const float inv = 1.f / l[i];
        const size_t idx = base + (size_t)(q0 + ty * 4 + i) * D_MODEL + tx * 4;
        half2 h01, l01, h23, l23;
        split_h2(o[i][0] * inv, o[i][1] * inv, h01, l01);
        split_h2(o[i][2] * inv, o[i][3] * inv, h23, l23);
        *(uint2*)(O_hi + idx) = make_uint2(*(uint32_t*)&h01, *(uint32_t*)&h23);
        *(uint2*)(O_lo + idx) = make_uint2(*(uint32_t*)&l01, *(uint32_t*)&l23);
    }
}

/* ------------------------------- launch -------------------------------- */
extern "C" void kernel_launch(void* const* d_in, const int* in_sizes, int n_in,
                              void* d_out, int out_size)
{
    const float* x  = (const float*)d_in[0];
    const float* wq = (const float*)d_in[1];
    const float* wk = (const float*)d_in[2];
    const float* wv = (const float*)d_in[3];
    const float* wo = (const float*)d_in[4];
    const float* bo = (const float*)d_in[5];
    const float* w1 = (const float*)d_in[6];
    const float* b1 = (const float*)d_in[7];
    const float* w2 = (const float*)d_in[8];
    const float* b2 = (const float*)d_in[9];
    const float* a1 = (const float*)d_in[10];
    const float* s1 = (const float*)d_in[11];
    const float* a2 = (const float*)d_in[12];
    const float* s2 = (const float*)d_in[13];
    float* out = (float*)d_out;

    float *q, *k, *v, *x2;
    cudaGetSymbolAddress((void**)&q,  g_q);
    cudaGetSymbolAddress((void**)&k,  g_k);
    cudaGetSymbolAddress((void**)&v,  g_v);
    cudaGetSymbolAddress((void**)&x2, g_x2);
    __half *h_hi, *h_lo, *ctx_hi, *ctx_lo, *h2_hi, *h2_lo, *ff_hi, *ff_lo;
    cudaGetSymbolAddress((void**)&h_hi,   g_h_hi);
    cudaGetSymbolAddress((void**)&h_lo,   g_h_lo);
    cudaGetSymbolAddress((void**)&ctx_hi, g_ctx_hi);
    cudaGetSymbolAddress((void**)&ctx_lo, g_ctx_lo);
    cudaGetSymbolAddress((void**)&h2_hi,  g_h2_hi);
    cudaGetSymbolAddress((void**)&h2_lo,  g_h2_lo);
    cudaGetSymbolAddress((void**)&ff_hi,  g_ff_hi);
    cudaGetSymbolAddress((void**)&ff_lo,  g_ff_lo);
    __half *wq_hi, *wq_lo, *wk_hi, *wk_lo, *wv_hi, *wv_lo;
    __half *wo_hi, *wo_lo, *w1_hi, *w1_lo, *w2_hi, *w2_lo;
    cudaGetSymbolAddress((void**)&wq_hi, g_wq_hi);
    cudaGetSymbolAddress((void**)&wq_lo, g_wq_lo);
    cudaGetSymbolAddress((void**)&wk_hi, g_wk_hi);
    cudaGetSymbolAddress((void**)&wk_lo, g_wk_lo);
    cudaGetSymbolAddress((void**)&wv_hi, g_wv_hi);
    cudaGetSymbolAddress((void**)&wv_lo, g_wv_lo);
    cudaGetSymbolAddress((void**)&wo_hi, g_wo_hi);
    cudaGetSymbolAddress((void**)&wo_lo, g_wo_lo);
    cudaGetSymbolAddress((void**)&w1_hi, g_w1_hi);
    cudaGetSymbolAddress((void**)&w1_lo, g_w1_lo);
    cudaGetSymbolAddress((void**)&w2_hi, g_w2_hi);
    cudaGetSymbolAddress((void**)&w2_lo, g_w2_lo);

    const int fa_smem = 3 * 64 * FLD * (int)sizeof(float);
    cudaFuncSetAttribute(flash_kernel,
                         cudaFuncAttributeMaxDynamicSharedMemorySize, fa_smem);
    cudaFuncSetAttribute(gemm_tc<EPI_NONE>,
                         cudaFuncAttributeMaxDynamicSharedMemorySize, GEMM_SMEM);
    cudaFuncSetAttribute(gemm_tc<EPI_BIAS_RES>,
                         cudaFuncAttributeMaxDynamicSharedMemorySize, GEMM_SMEM);
    cudaFuncSetAttribute(gemm_tc<EPI_BIAS_GELU>,
                         cudaFuncAttributeMaxDynamicSharedMemorySize, GEMM_SMEM);

    /* 0) convert all weights to fp16 hi/lo (one fused launch) */
    cvt6_kernel<<<12288, 256>>>(wq, wk, wv, wo, w1, w2,
                                wq_hi, wq_lo, wk_hi, wk_lo, wv_hi, wv_lo,
                                wo_hi, wo_lo, w1_hi, w1_lo, w2_hi, w2_lo);

    /* 1) h = LN(x) (hi/lo fp16) */
    ln_kernel<<<NROWS, 256>>>(x, a1, s1, h_hi, h_lo);

    /* 2) q/k/v = h @ W{q,k,v} (fp32 out) */
    dim3 g_dd(D_MODEL / BN, NROWS / BM);
    gemm_tc<EPI_NONE><<<g_dd, TC_THREADS, GEMM_SMEM>>>(
        h_hi, h_lo, wq_hi, wq_lo, nullptr, nullptr, q, nullptr, nullptr,
        NROWS, D_MODEL, D_MODEL);
    gemm_tc<EPI_NONE><<<g_dd, TC_THREADS, GEMM_SMEM>>>(
        h_hi, h_lo, wk_hi, wk_lo, nullptr, nullptr, k, nullptr, nullptr,
        NROWS, D_MODEL, D_MODEL);
    gemm_tc<EPI_NONE><<<g_dd, TC_THREADS, GEMM_SMEM>>>(
        h_hi, h_lo, wv_hi, wv_lo, nullptr, nullptr, v, nullptr, nullptr,
        NROWS, D_MODEL, D_MODEL);

    /* 3) causal flash attention -> ctx hi/lo */
    flash_kernel<<<dim3(SEQ / 64, NHEAD, BATCH), 256, fa_smem>>>(
        q, k, v, ctx_hi, ctx_lo);

    /* 4) x2 = x + ctx @ wo + bo (fp32) */
    gemm_tc<EPI_BIAS_RES><<<g_dd, TC_THREADS, GEMM_SMEM>>>(
        ctx_hi, ctx_lo, wo_hi, wo_lo, bo, x, x2, nullptr, nullptr,
        NROWS, D_MODEL, D_MODEL);

    /* 5) h2 = LN(x2) (hi/lo fp16) */
    ln_kernel<<<NROWS, 256>>>(x2, a2, s2, h2_hi, h2_lo);

    /* 6) ff = gelu(h2 @ w1 + b1) (hi/lo fp16) */
    gemm_tc<EPI_BIAS_GELU><<<dim3(FFDIM / BN, NROWS / BM), TC_THREADS, GEMM_SMEM>>>(
        h2_hi, h2_lo, w1_hi, w1_lo, b1, nullptr, nullptr, ff_hi, ff_lo,
        NROWS, FFDIM, D_MODEL);

    /* 7) out = x2 + ff @ w2 + b2 (fp32) */
    gemm_tc<EPI_BIAS_RES><<<g_dd, TC_THREADS, GEMM_SMEM>>>(
        ff_hi, ff_lo, w2_hi, w2_lo, b2, x2, out, nullptr, nullptr,
        NROWS, D_MODEL, FFDIM);
}

// round 16
// speedup vs baseline: 1.0102x; 1.0102x over previous
#include <cuda_runtime.h>
#include <cuda_fp16.h>
#include <math.h>
#include <stdint.h>

#define D_MODEL 1024
#define SEQ     2048
#define BATCH   2
#define NROWS   (BATCH*SEQ)   /* 4096 */
#define NHEAD   16
#define HD      64
#define FFDIM   4096
#define LN_EPS  1e-5f

/* ------------------- scratch (no allocations allowed) ------------------- */
__device__ float g_q  [NROWS*(size_t)D_MODEL];
__device__ float g_k  [NROWS*(size_t)D_MODEL];
__device__ float g_v  [NROWS*(size_t)D_MODEL];
__device__ float g_x2 [NROWS*(size_t)D_MODEL];
__device__ __half g_h_hi  [NROWS*(size_t)D_MODEL];
__device__ __half g_h_lo  [NROWS*(size_t)D_MODEL];
__device__ __half g_ctx_hi[NROWS*(size_t)D_MODEL];
__device__ __half g_ctx_lo[NROWS*(size_t)D_MODEL];
__device__ __half g_h2_hi [NROWS*(size_t)D_MODEL];
__device__ __half g_h2_lo [NROWS*(size_t)D_MODEL];
__device__ __half g_ff_hi [NROWS*(size_t)FFDIM];
__device__ __half g_ff_lo [NROWS*(size_t)FFDIM];
__device__ __half g_wq_hi[D_MODEL*(size_t)D_MODEL];
__device__ __half g_wq_lo[D_MODEL*(size_t)D_MODEL];
__device__ __half g_wk_hi[D_MODEL*(size_t)D_MODEL];
__device__ __half g_wk_lo[D_MODEL*(size_t)D_MODEL];
__device__ __half g_wv_hi[D_MODEL*(size_t)D_MODEL];
__device__ __half g_wv_lo[D_MODEL*(size_t)D_MODEL];
__device__ __half g_wo_hi[D_MODEL*(size_t)D_MODEL];
__device__ __half g_wo_lo[D_MODEL*(size_t)D_MODEL];
__device__ __half g_w1_hi[D_MODEL*(size_t)FFDIM];
__device__ __half g_w1_lo[D_MODEL*(size_t)FFDIM];
__device__ __half g_w2_hi[FFDIM*(size_t)D_MODEL];
__device__ __half g_w2_lo[FFDIM*(size_t)D_MODEL];

/* ============================ PTX helpers ============================ */
__device__ __forceinline__ uint32_t smem_u32(const void* p) {
    uint32_t a;
    asm("{ .reg .u64 t; cvta.to.shared.u64 t, %1; cvt.u32.u64 %0, t; }"
        : "=r"(a) : "l"(p));
    return a;
}
__device__ __forceinline__ void ldsm4(uint32_t r[4], uint32_t addr) {
    asm volatile("ldmatrix.sync.aligned.m8n8.x4.shared.b16 {%0,%1,%2,%3}, [%4];"
        : "=r"(r[0]), "=r"(r[1]), "=r"(r[2]), "=r"(r[3]) : "r"(addr));
}
__device__ __forceinline__ void ldsm4t(uint32_t r[4], uint32_t addr) {
    asm volatile("ldmatrix.sync.aligned.m8n8.x4.trans.shared.b16 {%0,%1,%2,%3}, [%4];"
        : "=r"(r[0]), "=r"(r[1]), "=r"(r[2]), "=r"(r[3]) : "r"(addr));
}
__device__ __forceinline__ void mma_f16(float d[4], const uint32_t a[4],
                                        const uint32_t b[2]) {
    asm volatile(
        "mma.sync.aligned.m16n8k16.row.col.f32.f16.f16.f32 "
        "{%0,%1,%2,%3}, {%4,%5,%6,%7}, {%8,%9}, {%0,%1,%2,%3};"
        : "+f"(d[0]), "+f"(d[1]), "+f"(d[2]), "+f"(d[3])
        : "r"(a[0]), "r"(a[1]), "r"(a[2]), "r"(a[3]), "r"(b[0]), "r"(b[1]));
}
__device__ __forceinline__ void cpa16(uint32_t dst, const void* src) {
    asm volatile("cp.async.cg.shared.global [%0], [%1], 16;"
                 :: "r"(dst), "l"(src) : "memory");
}
#define CP_COMMIT() asm volatile("cp.async.commit_group;" ::: "memory")
#define CP_WAIT(n)  asm volatile("cp.async.wait_group %0;" :: "n"(n) : "memory")

/* fp32 pair -> packed (hi half2, lo half2) */
__device__ __forceinline__ void split_h2(float x, float y, half2& hi, half2& lo) {
    __half hx = __float2half_rn(x), hy = __float2half_rn(y);
    hi = __halves2half2(hx, hy);
    lo = __floats2half2_rn(x - __half2float(hx), y - __half2float(hy));
}

/* ------------- fused weight fp32 -> hi/lo convert (6 arrays) ------------ */
#define DD4 (D_MODEL*D_MODEL/4)   /* 262144 -> 1024 blocks */
#define DF4 (D_MODEL*FFDIM/4)     /* 1048576 -> 4096 blocks */
__global__ __launch_bounds__(256) void cvt6_kernel(
    const float* __restrict__ wq, const float* __restrict__ wk,
    const float* __restrict__ wv, const float* __restrict__ wo,
    const float* __restrict__ w1, const float* __restrict__ w2,
    __half* qh, __half* ql, __half* kh, __half* kl, __half* vh, __half* vl,
    __half* oh, __half* ol, __half* h1p, __half* l1p, __half* h2p, __half* l2p)
{
    const int b = blockIdx.x;
    const float* in; __half* hi; __half* lo; int off;
    if      (b < 1024) { in = wq; hi = qh;  lo = ql;  off = b; }
    else if (b < 2048) { in = wk; hi = kh;  lo = kl;  off = b - 1024; }
    else if (b < 3072) { in = wv; hi = vh;  lo = vl;  off = b - 2048; }
    else if (b < 4096) { in = wo; hi = oh;  lo = ol;  off = b - 3072; }
    else if (b < 8192) { in = w1; hi = h1p; lo = l1p; off = b - 4096; }
    else               { in = w2; hi = h2p; lo = l2p; off = b - 8192; }
    const int i = off * 256 + threadIdx.x;
    const float4 v = ((const float4*)in)[i];
    half2 h01, l01, h23, l23;
    split_h2(v.x, v.y, h01, l01);
    split_h2(v.z, v.w, h23, l23);
    ((uint2*)hi)[i] = make_uint2(*(uint32_t*)&h01, *(uint32_t*)&h23);
    ((uint2*)lo)[i] = make_uint2(*(uint32_t*)&l01, *(uint32_t*)&l23);
}

/* --------------------- LayerNorm -> hi/lo fp16 out ---------------------- */
__global__ __launch_bounds__(256) void ln_kernel(
    const float* __restrict__ x, const float* __restrict__ alpha,
    const float* __restrict__ shift, __half* __restrict__ out_hi,
    __half* __restrict__ out_lo)
{
    const int row = blockIdx.x;
    const int tid = threadIdx.x;
    const float4 v = ((const float4*)(x + (size_t)row * D_MODEL))[tid];

    float s  = v.x + v.y + v.z + v.w;
    float ss = v.x*v.x + v.y*v.y + v.z*v.z + v.w*v.w;
    #pragma unroll
    for (int o = 16; o; o >>= 1) {
        s  += __shfl_xor_sync(0xffffffffu, s,  o);
        ss += __shfl_xor_sync(0xffffffffu, ss, o);
    }
    __shared__ float sm_s[8], sm_ss[8], sm_mean, sm_rstd;
    const int w = tid >> 5, lane = tid & 31;
    if (lane == 0) { sm_s[w] = s; sm_ss[w] = ss; }
    __syncthreads();
    if (w == 0) {
        float a = (lane < 8) ? sm_s[lane]  : 0.f;
        float b = (lane < 8) ? sm_ss[lane] : 0.f;
        #pragma unroll
        for (int o = 4; o; o >>= 1) {
            a += __shfl_xor_sync(0xffffffffu, a, o);
            b += __shfl_xor_sync(0xffffffffu, b, o);
        }
        if (lane == 0) {
            float mean = a * (1.f / D_MODEL);
            float var  = b * (1.f / D_MODEL) - mean * mean;
            sm_mean = mean;
            sm_rstd = rsqrtf(var + LN_EPS);
        }
    }
    __syncthreads();
    const float mean = sm_mean, rstd = sm_rstd;
    const float4 av = ((const float4*)alpha)[tid];
    const float4 sv = ((const float4*)shift)[tid];
    float4 ov;
    ov.x = av.x * (v.x - mean) * rstd + sv.x;
    ov.y = av.y * (v.y - mean) * rstd + sv.y;
    ov.z = av.z * (v.z - mean) * rstd + sv.z;
    ov.w = av.w * (v.w - mean) * rstd + sv.w;
    half2 h01, l01, h23, l23;
    split_h2(ov.x, ov.y, h01, l01);
    split_h2(ov.z, ov.w, h23, l23);
    ((uint2*)(out_hi + (size_t)row * D_MODEL))[tid] =
        make_uint2(*(uint32_t*)&h01, *(uint32_t*)&h23);
    ((uint2*)(out_lo + (size_t)row * D_MODEL))[tid] =
        make_uint2(*(uint32_t*)&l01, *(uint32_t*)&l23);
}

/* == mma.sync fp16-split GEMM, 128x128, BK=32, 2-stage, 2 CTAs/SM ======= */
enum { EPI_NONE = 0, EPI_BIAS_RES = 1, EPI_BIAS_GELU = 2 };

__device__ __forceinline__ float gelu_f(float x) {
    float t = tanhf(0.7978845608028654f * (x + 0.044715f * x * x * x));
    return 0.5f * x * (1.f + t);
}

#define BM 128
#define BN 128
#define BK 32
#define TC_THREADS 256
#define STAGES 2

/* per-stage smem layout (bytes):
   A_hi [128 x 80B] @0 ; A_lo @10240 ; B_hi [32 x 272B] @20480 ; B_lo @29184 */
#define A_PITCH   80
#define B_PITCH   272
#define A_LO_OFF  10240
#define B_HI_OFF  20480
#define B_LO_OFF  29184
#define STAGE_B   37888
#define GEMM_SMEM (STAGES*STAGE_B)   /* 75776 -> 2 CTAs/SM */

__device__ __forceinline__ void issue_stage(
    uint32_t st, const __half* __restrict__ Ah, const __half* __restrict__ Al,
    const __half* __restrict__ Bh, const __half* __restrict__ Bl,
    int row0, int col0, int k0, int K, int N, int tid)
{
    #pragma unroll
    for (int i = 0; i < 2; ++i) {
        const int ch = tid + i * TC_THREADS;
        const int r = ch >> 2, qa = ch & 3;
        const size_t ao = (size_t)(row0 + r) * K + k0 + qa * 8;
        cpa16(st + r * A_PITCH + qa * 16,            Ah + ao);
        cpa16(st + A_LO_OFF + r * A_PITCH + qa * 16, Al + ao);
        const int k = ch >> 4, qb = ch & 15;
        const size_t bo = (size_t)(k0 + k) * N + col0 + qb * 8;
        cpa16(st + B_HI_OFF + k * B_PITCH + qb * 16, Bh + bo);
        cpa16(st + B_LO_OFF + k * B_PITCH + qb * 16, Bl + bo);
    }
}

template<int EPI>
__global__ __launch_bounds__(TC_THREADS, 2) void gemm_tc(
    const __half* __restrict__ Ah, const __half* __restrict__ Al,
    const __half* __restrict__ Bh, const __half* __restrict__ Bl,
    const float* __restrict__ bias, const float* __restrict__ res,
    float* __restrict__ Cf, __half* __restrict__ Ch, __half* __restrict__ Cl,
    int M, int N, int K)
{
    extern __shared__ char smc[];
    const uint32_t sb = smem_u32(smc);
    const int tid  = threadIdx.x;
    const int wid  = tid >> 5, lane = tid & 31;
    const int warp_m = wid & 3, warp_n = wid >> 2;
    const int row0 = blockIdx.y * BM, col0 = blockIdx.x * BN;

    const uint32_t a_rel = (uint32_t)((warp_m * 32 + (lane & 15)) * A_PITCH
                                      + ((lane >> 4) << 4));
    const uint32_t b_rel = (uint32_t)(B_HI_OFF + (lane & 15) * B_PITCH
                                      + warp_n * 128 + ((lane >> 4) << 4));

    float acc[2][8][4];
    #pragma unroll
    for (int mt = 0; mt < 2; ++mt)
        #pragma unroll
        for (int nt = 0; nt < 8; ++nt)
            #pragma unroll
            for (int r = 0; r < 4; ++r) acc[mt][nt][r] = 0.f;

    const int nc = K / BK;

    issue_stage(sb, Ah, Al, Bh, Bl, row0, col0, 0, K, N, tid);
    CP_COMMIT();

    for (int c = 0; c < nc; ++c) {
        /* trailing sync of previous iter guarantees buffer (c+1)&1 is free */
        if (c + 1 < nc) {
            issue_stage(sb + ((c + 1) & 1) * STAGE_B,
                        Ah, Al, Bh, Bl, row0, col0, (c + 1) * BK, K, N, tid);
            CP_COMMIT();
        }
        CP_WAIT(1);          /* stage c landed (only stage c+1 in flight) */
        __syncthreads();

        const uint32_t st = sb + (uint32_t)((c & 1) * STAGE_B);
        #pragma unroll
        for (int ks = 0; ks < 2; ++ks) {
            uint32_t ah[2][4], al[2][4];
            #pragma unroll
            for (int mt = 0; mt < 2; ++mt) {
                ldsm4(ah[mt], st + a_rel + mt * (16*A_PITCH) + ks * 32);
                ldsm4(al[mt], st + a_rel + A_LO_OFF + mt * (16*A_PITCH) + ks * 32);
            }
            #pragma unroll
            for (int n2 = 0; n2 < 4; ++n2) {
                uint32_t th[4], tl[4];
                ldsm4t(th, st + b_rel + ks * (16*B_PITCH) + n2 * 32);
                ldsm4t(tl, st + b_rel + (B_LO_OFF-B_HI_OFF) + ks * (16*B_PITCH) + n2 * 32);
                #pragma unroll
                for (int mt = 0; mt < 2; ++mt) {
                    mma_f16(acc[mt][2*n2],   ah[mt], th);
                    mma_f16(acc[mt][2*n2],   ah[mt], tl);
                    mma_f16(acc[mt][2*n2],   al[mt], th);
                    mma_f16(acc[mt][2*n2+1], ah[mt], th + 2);
                    mma_f16(acc[mt][2*n2+1], ah[mt], tl + 2);
                    mma_f16(acc[mt][2*n2+1], al[mt], th + 2);
                }
            }
        }
        __syncthreads();     /* all warps done reading stage c */
    }

    /* epilogue */
    const int g = lane >> 2, t = lane & 3;
    #pragma unroll
    for (int mt = 0; mt < 2; ++mt) {
        #pragma unroll
        for (int nt = 0; nt < 8; ++nt) {
            const int r  = row0 + warp_m * 32 + mt * 16 + g;
            const int cx = col0 + warp_n * 64 + nt * 8 + t * 2;
            float2 v0 = make_float2(acc[mt][nt][0], acc[mt][nt][1]);
            float2 v1 = make_float2(acc[mt][nt][2], acc[mt][nt][3]);
            if (EPI == EPI_BIAS_RES) {
                const float2 bi = *(const float2*)(bias + cx);
                const float2 r0 = *(const float2*)(res + (size_t)r * N + cx);
                const float2 r1 = *(const float2*)(res + (size_t)(r + 8) * N + cx);
                v0.x += bi.x + r0.x; v0.y += bi.y + r0.y;
                v1.x += bi.x + r1.x; v1.y += bi.y + r1.y;
            }
            if (EPI == EPI_BIAS_GELU) {
                const float2 bi = *(const float2*)(bias + cx);
                v0.x = gelu_f(v0.x + bi.x); v0.y = gelu_f(v0.y + bi.y);
                v1.x = gelu_f(v1.x + bi.x); v1.y = gelu_f(v1.y + bi.y);
                half2 h0, l0, h1, l1;
                split_h2(v0.x, v0.y, h0, l0);
                split_h2(v1.x, v1.y, h1, l1);
                *(half2*)(Ch + (size_t)r * N + cx)       = h0;
                *(half2*)(Cl + (size_t)r * N + cx)       = l0;
                *(half2*)(Ch + (size_t)(r + 8) * N + cx) = h1;
                *(half2*)(Cl + (size_t)(r + 8) * N + cx) = l1;
            } else {
                *(float2*)(Cf + (size_t)r * N + cx)       = v0;
                *(float2*)(Cf + (size_t)(r + 8) * N + cx) = v1;
            }
        }
    }
}

/* ------------------- Flash attention (fp32, hi/lo out) ------------------ */
#define FLD 68

__global__ __launch_bounds__(256) void flash_kernel(
    const float* __restrict__ Q, const float* __restrict__ K,
    const float* __restrict__ V, __half* __restrict__ O_hi,
    __half* __restrict__ O_lo)
{
    extern __shared__ float sm[];
    float* QT = sm;
    float* KT = sm + 64 * FLD;
    float* VS = sm + 2 * 64 * FLD;

    const int tid = threadIdx.x;
    const int tx = tid & 15, ty = tid >> 4;
    const int q0 = blockIdx.x * 64;
    const int h = blockIdx.y, b = blockIdx.z;
    const size_t base = ((size_t)b * SEQ) * D_MODEL + (size_t)h * HD;

    const int lr  = tid >> 2;
    const int ld0 = (tid & 3) * 4;

    #pragma unroll
    for (int it = 0; it < 4; ++it) {
        const int d = ld0 + it * 16;
        float4 qv = *(const float4*)(Q + base + (size_t)(q0 + lr) * D_MODEL + d);
        QT[(d + 0) * FLD + lr] = qv.x;
        QT[(d + 1) * FLD + lr] = qv.y;
        QT[(d + 2) * FLD + lr] = qv.z;
        QT[(d + 3) * FLD + lr] = qv.w;
    }

    float m[4], l[4], o[4][4];
    #pragma unroll
    for (int i = 0; i < 4; i++) {
        m[i] = -INFINITY; l[i] = 0.f;
        #pragma unroll
        for (int j = 0; j < 4; j++) o[i][j] = 0.f;
    }

    const int ntiles = blockIdx.x + 1;
    for (int t = 0; t < ntiles; ++t) {
        const int k0 = t * 64;
        __syncthreads();
        #pragma unroll
        for (int it = 0; it < 4; ++it) {
            const int d = ld0 + it * 16;
            float4 kv = *(const float4*)(K + base + (size_t)(k0 + lr) * D_MODEL + d);
            KT[(d + 0) * FLD + lr] = kv.x;
            KT[(d + 1) * FLD + lr] = kv.y;
            KT[(d + 2) * FLD + lr] = kv.z;
            KT[(d + 3) * FLD + lr] = kv.w;
            float4 vv = *(const float4*)(V + base + (size_t)(k0 + lr) * D_MODEL + d);
            *(float4*)&VS[lr * FLD + d] = vv;
        }
        __syncthreads();

        float s[4][4];
        #pragma unroll
        for (int i = 0; i < 4; i++)
            #pragma unroll
            for (int j = 0; j < 4; j++) s[i][j] = 0.f;
        #pragma unroll 8
        for (int k = 0; k < 64; ++k) {
            float4 ra = *(const float4*)&QT[k * FLD + ty * 4];
            float4 rb = *(const float4*)&KT[k * FLD + tx * 4];
            float fa[4] = {ra.x, ra.y, ra.z, ra.w};
            float fb[4] = {rb.x, rb.y, rb.z, rb.w};
            #pragma unroll
            for (int i = 0; i < 4; i++)
                #pragma unroll
                for (int j = 0; j < 4; j++)
                    s[i][j] += fa[i] * fb[j];
        }
        const bool diag = (k0 == q0);
        #pragma unroll
        for (int i = 0; i < 4; i++)
            #pragma unroll
            for (int j = 0; j < 4; j++) {
                s[i][j] *= 0.125f;
                if (diag && (tx * 4 + j > ty * 4 + i)) s[i][j] = -INFINITY;
            }

        float pv[4][4];
        #pragma unroll
        for (int i = 0; i < 4; i++) {
            float rm = fmaxf(fmaxf(s[i][0], s[i][1]), fmaxf(s[i][2], s[i][3]));
            #pragma unroll
            for (int off = 1; off < 16; off <<= 1)
                rm = fmaxf(rm, __shfl_xor_sync(0xffffffffu, rm, off));
            const float nm = fmaxf(m[i], rm);
            const float alpha = __expf(m[i] - nm);
            m[i] = nm;
            float rs = 0.f;
            #pragma unroll
            for (int j = 0; j < 4; j++) {
                pv[i][j] = __expf(s[i][j] - nm);
                rs += pv[i][j];
            }
            #pragma unroll
            for (int off = 1; off < 16; off <<= 1)
                rs += __shfl_xor_sync(0xffffffffu, rs, off);
            l[i] = l[i] * alpha + rs;
            #pragma unroll
            for (int j = 0; j < 4; j++) o[i][j] *= alpha;
        }

        __syncthreads();
        #pragma unroll
        for (int i = 0; i < 4; i++)
            #pragma unroll
            for (int j = 0; j < 4; j++)
                KT[(tx * 4 + j) * FLD + ty * 4 + i] = pv[i][j];
        __syncthreads();

        #pragma unroll 8
        for (int kk = 0; kk < 64; ++kk) {
            float4 rp = *(const float4*)&KT[kk * FLD + ty * 4];
            float4 rv = *(const float4*)&VS[kk * FLD + tx * 4];
            float fp[4] = {rp.x, rp.y, rp.z, rp.w};
            float fv[4] = {rv.x, rv.y, rv.z, rv.w};
            #pragma unroll
            for (int i = 0; i < 4; i++)
                #pragma unroll
                for (int j = 0; j < 4; j++)
                    o[i][j] += fp[i] * fv[j];
        }
    }

    #pragma unroll
    for (int i = 0; i < 4; i++) {
        const float inv = 1.f / l[i];
        const size_t idx = base + (size_t)(q0 + ty * 4 + i) * D_MODEL + tx * 4;
        half2 h01, l01, h23, l23;
        split_h2(o[i][0] * inv, o[i][1] * inv, h01, l01);
        split_h2(o[i][2] * inv, o[i][3] * inv, h23, l23);
        *(uint2*)(O_hi + idx) = make_uint2(*(uint32_t*)&h01, *(uint32_t*)&h23);
        *(uint2*)(O_lo + idx) = make_uint2(*(uint32_t*)&l01, *(uint32_t*)&l23);
    }
}

/* ------------------------------- launch -------------------------------- */
extern "C" void kernel_launch(void* const* d_in, const int* in_sizes, int n_in,
                              void* d_out, int out_size)
{
    const float* x  = (const float*)d_in[0];
    const float* wq = (const float*)d_in[1];
    const float* wk = (const float*)d_in[2];
    const float* wv = (const float*)d_in[3];
    const float* wo = (const float*)d_in[4];
    const float* bo = (const float*)d_in[5];
    const float* w1 = (const float*)d_in[6];
    const float* b1 = (const float*)d_in[7];
    const float* w2 = (const float*)d_in[8];
    const float* b2 = (const float*)d_in[9];
    const float* a1 = (const float*)d_in[10];
    const float* s1 = (const float*)d_in[11];
    const float* a2 = (const float*)d_in[12];
    const float* s2 = (const float*)d_in[13];
    float* out = (float*)d_out;

    float *q, *k, *v, *x2;
    cudaGetSymbolAddress((void**)&q,  g_q);
    cudaGetSymbolAddress((void**)&k,  g_k);
    cudaGetSymbolAddress((void**)&v,  g_v);
    cudaGetSymbolAddress((void**)&x2, g_x2);
    __half *h_hi, *h_lo, *ctx_hi, *ctx_lo, *h2_hi, *h2_lo, *ff_hi, *ff_lo;
    cudaGetSymbolAddress((void**)&h_hi,   g_h_hi);
    cudaGetSymbolAddress((void**)&h_lo,   g_h_lo);
    cudaGetSymbolAddress((void**)&ctx_hi, g_ctx_hi);
    cudaGetSymbolAddress((void**)&ctx_lo, g_ctx_lo);
    cudaGetSymbolAddress((void**)&h2_hi,  g_h2_hi);
    cudaGetSymbolAddress((void**)&h2_lo,  g_h2_lo);
    cudaGetSymbolAddress((void**)&ff_hi,  g_ff_hi);
    cudaGetSymbolAddress((void**)&ff_lo,  g_ff_lo);
    __half *wq_hi, *wq_lo, *wk_hi, *wk_lo, *wv_hi, *wv_lo;
    __half *wo_hi, *wo_lo, *w1_hi, *w1_lo, *w2_hi, *w2_lo;
    cudaGetSymbolAddress((void**)&wq_hi, g_wq_hi);
    cudaGetSymbolAddress((void**)&wq_lo, g_wq_lo);
    cudaGetSymbolAddress((void**)&wk_hi, g_wk_hi);
    cudaGetSymbolAddress((void**)&wk_lo, g_wk_lo);
    cudaGetSymbolAddress((void**)&wv_hi, g_wv_hi);
    cudaGetSymbolAddress((void**)&wv_lo, g_wv_lo);
    cudaGetSymbolAddress((void**)&wo_hi, g_wo_hi);
    cudaGetSymbolAddress((void**)&wo_lo, g_wo_lo);
    cudaGetSymbolAddress((void**)&w1_hi, g_w1_hi);
    cudaGetSymbolAddress((void**)&w1_lo, g_w1_lo);
    cudaGetSymbolAddress((void**)&w2_hi, g_w2_hi);
    cudaGetSymbolAddress((void**)&w2_lo, g_w2_lo);

    const int fa_smem = 3 * 64 * FLD * (int)sizeof(float);
    cudaFuncSetAttribute(flash_kernel,
                         cudaFuncAttributeMaxDynamicSharedMemorySize, fa_smem);
    cudaFuncSetAttribute(gemm_tc<EPI_NONE>,
                         cudaFuncAttributeMaxDynamicSharedMemorySize, GEMM_SMEM);
    cudaFuncSetAttribute(gemm_tc<EPI_BIAS_RES>,
                         cudaFuncAttributeMaxDynamicSharedMemorySize, GEMM_SMEM);
    cudaFuncSetAttribute(gemm_tc<EPI_BIAS_GELU>,
                         cudaFuncAttributeMaxDynamicSharedMemorySize, GEMM_SMEM);

    /* 0) convert all weights to fp16 hi/lo (one fused launch) */
    cvt6_kernel<<<12288, 256>>>(wq, wk, wv, wo, w1, w2,
                                wq_hi, wq_lo, wk_hi, wk_lo, wv_hi, wv_lo,
                                wo_hi, wo_lo, w1_hi, w1_lo, w2_hi, w2_lo);

    /* 1) h = LN(x) (hi/lo fp16) */
    ln_kernel<<<NROWS, 256>>>(x, a1, s1, h_hi, h_lo);

    /* 2) q/k/v = h @ W{q,k,v} (fp32 out) */
    dim3 g_dd(D_MODEL / BN, NROWS / BM);
    gemm_tc<EPI_NONE><<<g_dd, TC_THREADS, GEMM_SMEM>>>(
        h_hi, h_lo, wq_hi, wq_lo, nullptr, nullptr, q, nullptr, nullptr,
        NROWS, D_MODEL, D_MODEL);
    gemm_tc<EPI_NONE><<<g_dd, TC_THREADS, GEMM_SMEM>>>(
        h_hi, h_lo, wk_hi, wk_lo, nullptr, nullptr, k, nullptr, nullptr,
        NROWS, D_MODEL, D_MODEL);
    gemm_tc<EPI_NONE><<<g_dd, TC_THREADS, GEMM_SMEM>>>(
        h_hi, h_lo, wv_hi, wv_lo, nullptr, nullptr, v, nullptr, nullptr,
        NROWS, D_MODEL, D_MODEL);

    /* 3) causal flash attention -> ctx hi/lo */
    flash_kernel<<<dim3(SEQ / 64, NHEAD, BATCH), 256, fa_smem>>>(
        q, k, v, ctx_hi, ctx_lo);

    /* 4) x2 = x + ctx @ wo + bo (fp32) */
    gemm_tc<EPI_BIAS_RES><<<g_dd, TC_THREADS, GEMM_SMEM>>>(
        ctx_hi, ctx_lo, wo_hi, wo_lo, bo, x, x2, nullptr, nullptr,
        NROWS, D_MODEL, D_MODEL);

    /* 5) h2 = LN(x2) (hi/lo fp16) */
    ln_kernel<<<NROWS, 256>>>(x2, a2, s2, h2_hi, h2_lo);

    /* 6) ff = gelu(h2 @ w1 + b1) (hi/lo fp16) */
    gemm_tc<EPI_BIAS_GELU><<<dim3(FFDIM / BN, NROWS / BM), TC_THREADS, GEMM_SMEM>>>(
        h2_hi, h2_lo, w1_hi, w1_lo, b1, nullptr, nullptr, ff_hi, ff_lo,
        NROWS, FFDIM, D_MODEL);

    /* 7) out = x2 + ff @ w2 + b2 (fp32) */
    gemm_tc<EPI_BIAS_RES><<<g_dd, TC_THREADS, GEMM_SMEM>>>(
        ff_hi, ff_lo, w2_hi, w2_lo, b2, x2, out, nullptr, nullptr,
        NROWS, D_MODEL, FFDIM);
}

// round 17
// speedup vs baseline: 1.3842x; 1.3702x over previous
#include <cuda_runtime.h>
#include <cuda_fp16.h>
#include <math.h>
#include <stdint.h>

#define D_MODEL 1024
#define SEQ     2048
#define BATCH   2
#define NROWS   (BATCH*SEQ)   /* 4096 */
#define NHEAD   16
#define HD      64
#define FFDIM   4096
#define LN_EPS  1e-5f

/* ------------------- scratch (no allocations allowed) ------------------- */
__device__ float  g_x2 [NROWS*(size_t)D_MODEL];
__device__ __half g_h_hi  [NROWS*(size_t)D_MODEL];
__device__ __half g_h_lo  [NROWS*(size_t)D_MODEL];
__device__ __half g_q_hi  [NROWS*(size_t)D_MODEL];
__device__ __half g_q_lo  [NROWS*(size_t)D_MODEL];
__device__ __half g_k_hi  [NROWS*(size_t)D_MODEL];
__device__ __half g_k_lo  [NROWS*(size_t)D_MODEL];
__device__ __half g_v_hi  [NROWS*(size_t)D_MODEL];
__device__ __half g_v_lo  [NROWS*(size_t)D_MODEL];
__device__ __half g_ctx_hi[NROWS*(size_t)D_MODEL];
__device__ __half g_ctx_lo[NROWS*(size_t)D_MODEL];
__device__ __half g_h2_hi [NROWS*(size_t)D_MODEL];
__device__ __half g_h2_lo [NROWS*(size_t)D_MODEL];
__device__ __half g_ff_hi [NROWS*(size_t)FFDIM];
__device__ __half g_ff_lo [NROWS*(size_t)FFDIM];
__device__ __half g_wq_hi[D_MODEL*(size_t)D_MODEL];
__device__ __half g_wq_lo[D_MODEL*(size_t)D_MODEL];
__device__ __half g_wk_hi[D_MODEL*(size_t)D_MODEL];
__device__ __half g_wk_lo[D_MODEL*(size_t)D_MODEL];
__device__ __half g_wv_hi[D_MODEL*(size_t)D_MODEL];
__device__ __half g_wv_lo[D_MODEL*(size_t)D_MODEL];
__device__ __half g_wo_hi[D_MODEL*(size_t)D_MODEL];
__device__ __half g_wo_lo[D_MODEL*(size_t)D_MODEL];
__device__ __half g_w1_hi[D_MODEL*(size_t)FFDIM];
__device__ __half g_w1_lo[D_MODEL*(size_t)FFDIM];
__device__ __half g_w2_hi[FFDIM*(size_t)D_MODEL];
__device__ __half g_w2_lo[FFDIM*(size_t)D_MODEL];

/* ============================ PTX helpers ============================ */
__device__ __forceinline__ uint32_t smem_u32(const void* p) {
    uint32_t a;
    asm("{ .reg .u64 t; cvta.to.shared.u64 t, %1; cvt.u32.u64 %0, t; }"
        : "=r"(a) : "l"(p));
    return a;
}
__device__ __forceinline__ void ldsm4(uint32_t r[4], uint32_t addr) {
    asm volatile("ldmatrix.sync.aligned.m8n8.x4.shared.b16 {%0,%1,%2,%3}, [%4];"
        : "=r"(r[0]), "=r"(r[1]), "=r"(r[2]), "=r"(r[3]) : "r"(addr));
}
__device__ __forceinline__ void ldsm4t(uint32_t r[4], uint32_t addr) {
    asm volatile("ldmatrix.sync.aligned.m8n8.x4.trans.shared.b16 {%0,%1,%2,%3}, [%4];"
        : "=r"(r[0]), "=r"(r[1]), "=r"(r[2]), "=r"(r[3]) : "r"(addr));
}
__device__ __forceinline__ void mma_f16(float d[4], const uint32_t a[4],
                                        const uint32_t b[2]) {
    asm volatile(
        "mma.sync.aligned.m16n8k16.row.col.f32.f16.f16.f32 "
        "{%0,%1,%2,%3}, {%4,%5,%6,%7}, {%8,%9}, {%0,%1,%2,%3};"
        : "+f"(d[0]), "+f"(d[1]), "+f"(d[2]), "+f"(d[3])
        : "r"(a[0]), "r"(a[1]), "r"(a[2]), "r"(a[3]), "r"(b[0]), "r"(b[1]));
}
__device__ __forceinline__ void cpa16(uint32_t dst, const void* src) {
    asm volatile("cp.async.cg.shared.global [%0], [%1], 16;"
                 :: "r"(dst), "l"(src) : "memory");
}
#define CP_COMMIT() asm volatile("cp.async.commit_group;" ::: "memory")
#define CP_WAIT(n)  asm volatile("cp.async.wait_group %0;" :: "n"(n) : "memory")

/* fp32 pair -> packed (hi half2, lo half2) */
__device__ __forceinline__ void split_h2(float x, float y, half2& hi, half2& lo) {
    __half hx = __float2half_rn(x), hy = __float2half_rn(y);
    hi = __halves2half2(hx, hy);
    lo = __floats2half2_rn(x - __half2float(hx), y - __half2float(hy));
}

/* ------------- fused weight fp32 -> hi/lo convert (6 arrays) ------------ */
__global__ __launch_bounds__(256) void cvt6_kernel(
    const float* __restrict__ wq, const float* __restrict__ wk,
    const float* __restrict__ wv, const float* __restrict__ wo,
    const float* __restrict__ w1, const float* __restrict__ w2,
    __half* qh, __half* ql, __half* kh, __half* kl, __half* vh, __half* vl,
    __half* oh, __half* ol, __half* h1p, __half* l1p, __half* h2p, __half* l2p)
{
    const int b = blockIdx.x;
    const float* in; __half* hi; __half* lo; int off;
    if      (b < 1024) { in = wq; hi = qh;  lo = ql;  off = b; }
    else if (b < 2048) { in = wk; hi = kh;  lo = kl;  off = b - 1024; }
    else if (b < 3072) { in = wv; hi = vh;  lo = vl;  off = b - 2048; }
    else if (b < 4096) { in = wo; hi = oh;  lo = ol;  off = b - 3072; }
    else if (b < 8192) { in = w1; hi = h1p; lo = l1p; off = b - 4096; }
    else               { in = w2; hi = h2p; lo = l2p; off = b - 8192; }
    const int i = off * 256 + threadIdx.x;
    const float4 v = ((const float4*)in)[i];
    half2 h01, l01, h23, l23;
    split_h2(v.x, v.y, h01, l01);
    split_h2(v.z, v.w, h23, l23);
    ((uint2*)hi)[i] = make_uint2(*(uint32_t*)&h01, *(uint32_t*)&h23);
    ((uint2*)lo)[i] = make_uint2(*(uint32_t*)&l01, *(uint32_t*)&l23);
}

/* --------------------- LayerNorm -> hi/lo fp16 out ---------------------- */
__global__ __launch_bounds__(256) void ln_kernel(
    const float* __restrict__ x, const float* __restrict__ alpha,
    const float* __restrict__ shift, __half* __restrict__ out_hi,
    __half* __restrict__ out_lo)
{
    const int row = blockIdx.x;
    const int tid = threadIdx.x;
    const float4 v = ((const float4*)(x + (size_t)row * D_MODEL))[tid];

    float s  = v.x + v.y + v.z + v.w;
    float ss = v.x*v.x + v.y*v.y + v.z*v.z + v.w*v.w;
    #pragma unroll
    for (int o = 16; o; o >>= 1) {
        s  += __shfl_xor_sync(0xffffffffu, s,  o);
        ss += __shfl_xor_sync(0xffffffffu, ss, o);
    }
    __shared__ float sm_s[8], sm_ss[8], sm_mean, sm_rstd;
    const int w = tid >> 5, lane = tid & 31;
    if (lane == 0) { sm_s[w] = s; sm_ss[w] = ss; }
    __syncthreads();
    if (w == 0) {
        float a = (lane < 8) ? sm_s[lane]  : 0.f;
        float b = (lane < 8) ? sm_ss[lane] : 0.f;
        #pragma unroll
        for (int o = 4; o; o >>= 1) {
            a += __shfl_xor_sync(0xffffffffu, a, o);
            b += __shfl_xor_sync(0xffffffffu, b, o);
        }
        if (lane == 0) {
            float mean = a * (1.f / D_MODEL);
            float var  = b * (1.f / D_MODEL) - mean * mean;
            sm_mean = mean;
            sm_rstd = rsqrtf(var + LN_EPS);
        }
    }
    __syncthreads();
    const float mean = sm_mean, rstd = sm_rstd;
    const float4 av = ((const float4*)alpha)[tid];
    const float4 sv = ((const float4*)shift)[tid];
    float4 ov;
    ov.x = av.x * (v.x - mean) * rstd + sv.x;
    ov.y = av.y * (v.y - mean) * rstd + sv.y;
    ov.z = av.z * (v.z - mean) * rstd + sv.z;
    ov.w = av.w * (v.w - mean) * rstd + sv.w;
    half2 h01, l01, h23, l23;
    split_h2(ov.x, ov.y, h01, l01);
    split_h2(ov.z, ov.w, h23, l23);
    ((uint2*)(out_hi + (size_t)row * D_MODEL))[tid] =
        make_uint2(*(uint32_t*)&h01, *(uint32_t*)&h23);
    ((uint2*)(out_lo + (size_t)row * D_MODEL))[tid] =
        make_uint2(*(uint32_t*)&l01, *(uint32_t*)&l23);
}

/* == mma.sync fp16-split GEMM, 128x128, BK=32, 2-stage, 2 CTAs/SM ======= */
enum { EPI_NONE = 0, EPI_BIAS_RES = 1, EPI_BIAS_GELU = 2, EPI_SPLIT = 3 };

__device__ __forceinline__ float gelu_f(float x) {
    float t = tanhf(0.7978845608028654f * (x + 0.044715f * x * x * x));
    return 0.5f * x * (1.f + t);
}

#define BM 128
#define BN 128
#define BK 32
#define TC_THREADS 256
#define STAGES 2

#define A_PITCH   80
#define B_PITCH   272
#define A_LO_OFF  10240
#define B_HI_OFF  20480
#define B_LO_OFF  29184
#define STAGE_B   37888
#define GEMM_SMEM (STAGES*STAGE_B)   /* 75776 -> 2 CTAs/SM */

__device__ __forceinline__ void issue_stage(
    uint32_t st, const __half* __restrict__ Ah, const __half* __restrict__ Al,
    const __half* __restrict__ Bh, const __half* __restrict__ Bl,
    int row0, int col0, int k0, int K, int N, int tid)
{
    #pragma unroll
    for (int i = 0; i < 2; ++i) {
        const int ch = tid + i * TC_THREADS;
        const int r = ch >> 2, qa = ch & 3;
        const size_t ao = (size_t)(row0 + r) * K + k0 + qa * 8;
        cpa16(st + r * A_PITCH + qa * 16,            Ah + ao);
        cpa16(st + A_LO_OFF + r * A_PITCH + qa * 16, Al + ao);
        const int k = ch >> 4, qb = ch & 15;
        const size_t bo = (size_t)(k0 + k) * N + col0 + qb * 8;
        cpa16(st + B_HI_OFF + k * B_PITCH + qb * 16, Bh + bo);
        cpa16(st + B_LO_OFF + k * B_PITCH + qb * 16, Bl + bo);
    }
}

template<int EPI>
__global__ __launch_bounds__(TC_THREADS, 2) void gemm_tc(
    const __half* __restrict__ Ah, const __half* __restrict__ Al,
    const __half* __restrict__ Bh, const __half* __restrict__ Bl,
    const float* __restrict__ bias, const float* __restrict__ res,
    float* __restrict__ Cf, __half* __restrict__ Ch, __half* __restrict__ Cl,
    int M, int N, int K)
{
    extern __shared__ char smc[];
    const uint32_t sb = smem_u32(smc);
    const int tid  = threadIdx.x;
    const int wid  = tid >> 5, lane = tid & 31;
    const int warp_m = wid & 3, warp_n = wid >> 2;
    const int row0 = blockIdx.y * BM, col0 = blockIdx.x * BN;

    const uint32_t a_rel = (uint32_t)((warp_m * 32 + (lane & 15)) * A_PITCH
                                      + ((lane >> 4) << 4));
    const uint32_t b_rel = (uint32_t)(B_HI_OFF + (lane & 15) * B_PITCH
                                      + warp_n * 128 + ((lane >> 4) << 4));

    float acc[2][8][4];
    #pragma unroll
    for (int mt = 0; mt < 2; ++mt)
        #pragma unroll
        for (int nt = 0; nt < 8; ++nt)
            #pragma unroll
            for (int r = 0; r < 4; ++r) acc[mt][nt][r] = 0.f;

    const int nc = K / BK;

    issue_stage(sb, Ah, Al, Bh, Bl, row0, col0, 0, K, N, tid);
    CP_COMMIT();

    for (int c = 0; c < nc; ++c) {
        if (c + 1 < nc) {
            issue_stage(sb + ((c + 1) & 1) * STAGE_B,
                        Ah, Al, Bh, Bl, row0, col0, (c + 1) * BK, K, N, tid);
            CP_COMMIT();
            CP_WAIT(1);      /* 2 groups in flight -> stage c complete */
        } else {
            CP_WAIT(0);      /* last chunk: drain fully (correctness!) */
        }
        __syncthreads();

        const uint32_t st = sb + (uint32_t)((c & 1) * STAGE_B);
        #pragma unroll
        for (int ks = 0; ks < 2; ++ks) {
            uint32_t ah[2][4], al[2][4];
            #pragma unroll
            for (int mt = 0; mt < 2; ++mt) {
                ldsm4(ah[mt], st + a_rel + mt * (16*A_PITCH) + ks * 32);
                ldsm4(al[mt], st + a_rel + A_LO_OFF + mt * (16*A_PITCH) + ks * 32);
            }
            #pragma unroll
            for (int n2 = 0; n2 < 4; ++n2) {
                uint32_t th[4], tl[4];
                ldsm4t(th, st + b_rel + ks * (16*B_PITCH) + n2 * 32);
                ldsm4t(tl, st + b_rel + (B_LO_OFF-B_HI_OFF) + ks * (16*B_PITCH) + n2 * 32);
                #pragma unroll
                for (int mt = 0; mt < 2; ++mt) {
                    mma_f16(acc[mt][2*n2],   ah[mt], th);
                    mma_f16(acc[mt][2*n2],   ah[mt], tl);
                    mma_f16(acc[mt][2*n2],   al[mt], th);
                    mma_f16(acc[mt][2*n2+1], ah[mt], th + 2);
                    mma_f16(acc[mt][2*n2+1], ah[mt], tl + 2);
                    mma_f16(acc[mt][2*n2+1], al[mt], th + 2);
                }
            }
        }
        __syncthreads();
    }

    /* epilogue */
    const int g = lane >> 2, t = lane & 3;
    #pragma unroll
    for (int mt = 0; mt < 2; ++mt) {
        #pragma unroll
        for (int nt = 0; nt < 8; ++nt) {
            const int r  = row0 + warp_m * 32 + mt * 16 + g;
            const int cx = col0 + warp_n * 64 + nt * 8 + t * 2;
            float2 v0 = make_float2(acc[mt][nt][0], acc[mt][nt][1]);
            float2 v1 = make_float2(acc[mt][nt][2], acc[mt][nt][3]);
            if (EPI == EPI_BIAS_RES) {
                const float2 bi = *(const float2*)(bias + cx);
                const float2 r0 = *(const float2*)(res + (size_t)r * N + cx);
                const float2 r1 = *(const float2*)(res + (size_t)(r + 8) * N + cx);
                v0.x += bi.x + r0.x; v0.y += bi.y + r0.y;
                v1.x += bi.x + r1.x; v1.y += bi.y + r1.y;
                *(float2*)(Cf + (size_t)r * N + cx)       = v0;
                *(float2*)(Cf + (size_t)(r + 8) * N + cx) = v1;
            } else if (EPI == EPI_BIAS_GELU || EPI == EPI_SPLIT) {
                if (EPI == EPI_BIAS_GELU) {
                    const float2 bi = *(const float2*)(bias + cx);
                    v0.x = gelu_f(v0.x + bi.x); v0.y = gelu_f(v0.y + bi.y);
                    v1.x = gelu_f(v1.x + bi.x); v1.y = gelu_f(v1.y + bi.y);
                }
                half2 h0, l0, h1, l1;
                split_h2(v0.x, v0.y, h0, l0);
                split_h2(v1.x, v1.y, h1, l1);
                *(half2*)(Ch + (size_t)r * N + cx)       = h0;
                *(half2*)(Cl + (size_t)r * N + cx)       = l0;
                *(half2*)(Ch + (size_t)(r + 8) * N + cx) = h1;
                *(half2*)(Cl + (size_t)(r + 8) * N + cx) = l1;
            } else {
                *(float2*)(Cf + (size_t)r * N + cx)       = v0;
                *(float2*)(Cf + (size_t)(r + 8) * N + cx) = v1;
            }
        }
    }
}

/* ============ Flash attention on mma.sync (fp16 hi/lo 3-pass) ============ */
/* CTA: 128 q-rows, 8 warps x 16 rows. KV tiles of 64, double-buffered.     */
#define FA_PITCH 144                 /* 64 halves + 16B pad */
#define FA_MAT   (64*FA_PITCH)       /* 9216 */
#define FA_STAGE (4*FA_MAT)          /* Kh,Kl,Vh,Vl = 36864 */
#define FA_SMEM  (2*FA_STAGE)        /* 73728 */

__device__ __forceinline__ void fa_issue_kv(
    uint32_t st, const __half* __restrict__ Kh, const __half* __restrict__ Kl,
    const __half* __restrict__ Vh, const __half* __restrict__ Vl,
    size_t rowbase, int colbase, int k0, int tid)
{
    #pragma unroll
    for (int i = 0; i < 2; ++i) {
        const int ch = tid + i * 256;
        const int r = ch >> 3, c = ch & 7;
        const size_t go = (rowbase + k0 + r) * D_MODEL + colbase + c * 8;
        const uint32_t so = r * FA_PITCH + c * 16;
        cpa16(st + so,            Kh + go);
        cpa16(st + FA_MAT + so,   Kl + go);
        cpa16(st + 2*FA_MAT + so, Vh + go);
        cpa16(st + 3*FA_MAT + so, Vl + go);
    }
}

__global__ __launch_bounds__(256) void flash_mma(
    const __half* __restrict__ Qh, const __half* __restrict__ Ql,
    const __half* __restrict__ Kh, const __half* __restrict__ Kl,
    const __half* __restrict__ Vh, const __half* __restrict__ Vl,
    __half* __restrict__ Oh, __half* __restrict__ Ol)
{
    extern __shared__ char smc[];
    const uint32_t sb = smem_u32(smc);
    const int tid = threadIdx.x, wid = tid >> 5, lane = tid & 31;
    const int qb = blockIdx.x, h = blockIdx.y, b = blockIdx.z;
    const int q0 = qb * 128;
    const size_t rowbase = (size_t)b * SEQ;
    const int colbase = h * HD;

    /* ---- stage Q tile (128x64 hi/lo) through smem into registers ---- */
    #pragma unroll
    for (int i = 0; i < 4; ++i) {
        const int ch = tid + i * 256;
        const int r = ch >> 3, c = ch & 7;
        const size_t go = (rowbase + q0 + r) * D_MODEL + colbase + c * 8;
        cpa16(sb + r * FA_PITCH + c * 16, Qh + go);
        cpa16(sb + 2*FA_MAT + r * FA_PITCH + c * 16, Ql + go);
    }
    CP_COMMIT();
    CP_WAIT(0);
    __syncthreads();

    const uint32_t lrel = (lane & 15) * FA_PITCH + ((lane >> 4) << 4);
    uint32_t qfh[4][4], qfl[4][4];
    {
        const uint32_t qa = sb + (wid * 16) * FA_PITCH + lrel;
        #pragma unroll
        for (int s = 0; s < 4; ++s) {
            ldsm4(qfh[s], qa + s * 32);
            ldsm4(qfl[s], qa + 2*FA_MAT + s * 32);
        }
    }
    __syncthreads();   /* Q fully in registers; smem free for KV */

    float oacc[8][4];
    #pragma unroll
    for (int j = 0; j < 8; ++j)
        #pragma unroll
        for (int e = 0; e < 4; ++e) oacc[j][e] = 0.f;
    float mrow[2] = {-INFINITY, -INFINITY};
    float lrow[2] = {0.f, 0.f};

    const int ntiles = 2 * qb + 2;
    const int wrow = q0 + wid * 16;
    const int g = lane >> 2, t2 = (lane & 3) * 2;

    fa_issue_kv(sb, Kh, Kl, Vh, Vl, rowbase, colbase, 0, tid);
    CP_COMMIT();

    for (int t = 0; t < ntiles; ++t) {
        if (t + 1 < ntiles) {
            fa_issue_kv(sb + ((t + 1) & 1) * FA_STAGE,
                        Kh, Kl, Vh, Vl, rowbase, colbase, (t + 1) * 64, tid);
            CP_COMMIT();
            CP_WAIT(1);
        } else {
            CP_WAIT(0);
        }
        __syncthreads();

        const uint32_t st = sb + (uint32_t)((t & 1) * FA_STAGE);
        const int k0 = t * 64;

        if (k0 <= wrow + 15) {   /* warp has unmasked work in this tile */
            /* ---- S = Q K^T (3-pass) ---- */
            float sacc[8][4];
            #pragma unroll
            for (int j = 0; j < 8; ++j)
                #pragma unroll
                for (int e = 0; e < 4; ++e) sacc[j][e] = 0.f;

            #pragma unroll
            for (int s = 0; s < 4; ++s) {
                #pragma unroll
                for (int r = 0; r < 4; ++r) {
                    uint32_t kh4[4], kl4[4];
                    const uint32_t ka = st + (r * 16) * FA_PITCH + lrel + s * 32;
                    ldsm4(kh4, ka);
                    ldsm4(kl4, ka + FA_MAT);
                    uint32_t bh0[2] = {kh4[0], kh4[2]}, bh1[2] = {kh4[1], kh4[3]};
                    uint32_t bl0[2] = {kl4[0], kl4[2]}, bl1[2] = {kl4[1], kl4[3]};
                    mma_f16(sacc[2*r],   qfh[s], bh0);
                    mma_f16(sacc[2*r],   qfh[s], bl0);
                    mma_f16(sacc[2*r],   qfl[s], bh0);
                    mma_f16(sacc[2*r+1], qfh[s], bh1);
                    mma_f16(sacc[2*r+1], qfh[s], bl1);
                    mma_f16(sacc[2*r+1], qfl[s], bh1);
                }
            }

            /* ---- scale + causal mask ---- */
            const bool need_mask = (k0 + 63 > wrow);
            #pragma unroll
            for (int j = 0; j < 8; ++j)
                #pragma unroll
                for (int e = 0; e < 4; ++e) {
                    float sv = sacc[j][e] * 0.125f;
                    if (need_mask) {
                        const int col = k0 + j * 8 + t2 + (e & 1);
                        const int row = wrow + g + (e >> 1) * 8;
                        if (col > row) sv = -INFINITY;
                    }
                    sacc[j][e] = sv;
                }

            /* ---- online softmax (rows g, g+8) ---- */
            float rmax[2] = {-INFINITY, -INFINITY};
            #pragma unroll
            for (int j = 0; j < 8; ++j) {
                rmax[0] = fmaxf(rmax[0], fmaxf(sacc[j][0], sacc[j][1]));
                rmax[1] = fmaxf(rmax[1], fmaxf(sacc[j][2], sacc[j][3]));
            }
            #pragma unroll
            for (int o = 1; o < 4; o <<= 1) {
                rmax[0] = fmaxf(rmax[0], __shfl_xor_sync(0xffffffffu, rmax[0], o));
                rmax[1] = fmaxf(rmax[1], __shfl_xor_sync(0xffffffffu, rmax[1], o));
            }
            float alpha[2], psum[2] = {0.f, 0.f};
            #pragma unroll
            for (int r = 0; r < 2; ++r) {
                const float nm = fmaxf(mrow[r], rmax[r]);
                alpha[r] = __expf(mrow[r] - nm);
                mrow[r] = nm;
            }
            #pragma unroll
            for (int j = 0; j < 8; ++j) {
                sacc[j][0] = __expf(sacc[j][0] - mrow[0]);
                sacc[j][1] = __expf(sacc[j][1] - mrow[0]);
                sacc[j][2] = __expf(sacc[j][2] - mrow[1]);
                sacc[j][3] = __expf(sacc[j][3] - mrow[1]);
                psum[0] += sacc[j][0] + sacc[j][1];
                psum[1] += sacc[j][2] + sacc[j][3];
            }
            #pragma unroll
            for (int o = 1; o < 4; o <<= 1) {
                psum[0] += __shfl_xor_sync(0xffffffffu, psum[0], o);
                psum[1] += __shfl_xor_sync(0xffffffffu, psum[1], o);
            }
            #pragma unroll
            for (int r = 0; r < 2; ++r)
                lrow[r] = lrow[r] * alpha[r] + psum[r];
            #pragma unroll
            for (int j = 0; j < 8; ++j) {
                oacc[j][0] *= alpha[0]; oacc[j][1] *= alpha[0];
                oacc[j][2] *= alpha[1]; oacc[j][3] *= alpha[1];
            }

            /* ---- P -> fp16 hi/lo A-fragments ---- */
            uint32_t pfh[4][4], pfl[4][4];
            #pragma unroll
            for (int s = 0; s < 4; ++s) {
                half2 hh, ll;
                split_h2(sacc[2*s][0],   sacc[2*s][1],   hh, ll);
                pfh[s][0] = *(uint32_t*)&hh; pfl[s][0] = *(uint32_t*)&ll;
                split_h2(sacc[2*s][2],   sacc[2*s][3],   hh, ll);
                pfh[s][1] = *(uint32_t*)&hh; pfl[s][1] = *(uint32_t*)&ll;
                split_h2(sacc[2*s+1][0], sacc[2*s+1][1], hh, ll);
                pfh[s][2] = *(uint32_t*)&hh; pfl[s][2] = *(uint32_t*)&ll;
                split_h2(sacc[2*s+1][2], sacc[2*s+1][3], hh, ll);
                pfh[s][3] = *(uint32_t*)&hh; pfl[s][3] = *(uint32_t*)&ll;
            }

            /* ---- O += P V (3-pass) ---- */
            #pragma unroll
            for (int s = 0; s < 4; ++s) {
                #pragma unroll
                for (int n2 = 0; n2 < 4; ++n2) {
                    uint32_t vh4[4], vl4[4];
                    const uint32_t va = st + 2*FA_MAT + (s * 16) * FA_PITCH
                                        + lrel + n2 * 32;
                    ldsm4t(vh4, va);
                    ldsm4t(vl4, va + FA_MAT);
                    mma_f16(oacc[2*n2],   pfh[s], vh4);
                    mma_f16(oacc[2*n2],   pfh[s], vl4);
                    mma_f16(oacc[2*n2],   pfl[s], vh4);
                    mma_f16(oacc[2*n2+1], pfh[s], vh4 + 2);
                    mma_f16(oacc[2*n2+1], pfh[s], vl4 + 2);
                    mma_f16(oacc[2*n2+1], pfl[s], vh4 + 2);
                }
            }
        }
        __syncthreads();
    }

    /* ---- write ctx hi/lo ---- */
    const float inv0 = 1.f / lrow[0], inv1 = 1.f / lrow[1];
    const size_t ro0 = (rowbase + wrow + g) * D_MODEL + colbase + t2;
    const size_t ro1 = (rowbase + wrow + g + 8) * D_MODEL + colbase + t2;
    #pragma unroll
    for (int j = 0; j < 8; ++j) {
        half2 hh, ll;
        split_h2(oacc[j][0] * inv0, oacc[j][1] * inv0, hh, ll);
        *(half2*)(Oh + ro0 + j * 8) = hh;
        *(half2*)(Ol + ro0 + j * 8) = ll;
        split_h2(oacc[j][2] * inv1, oacc[j][3] * inv1, hh, ll);
        *(half2*)(Oh + ro1 + j * 8) = hh;
        *(half2*)(Ol + ro1 + j * 8) = ll;
    }
}

/* ------------------------------- launch -------------------------------- */
extern "C" void kernel_launch(void* const* d_in, const int* in_sizes, int n_in,
                              void* d_out, int out_size)
{
    const float* x  = (const float*)d_in[0];
    const float* wq = (const float*)d_in[1];
    const float* wk = (const float*)d_in[2];
    const float* wv = (const float*)d_in[3];
    const float* wo = (const float*)d_in[4];
    const float* bo = (const float*)d_in[5];
    const float* w1 = (const float*)d_in[6];
    const float* b1 = (const float*)d_in[7];
    const float* w2 = (const float*)d_in[8];
    const float* b2 = (const float*)d_in[9];
    const float* a1 = (const float*)d_in[10];
    const float* s1 = (const float*)d_in[11];
    const float* a2 = (const float*)d_in[12];
    const float* s2 = (const float*)d_in[13];
    float* out = (float*)d_out;

    float* x2;
    cudaGetSymbolAddress((void**)&x2, g_x2);
    __half *h_hi, *h_lo, *q_hi, *q_lo, *k_hi, *k_lo, *v_hi, *v_lo;
    __half *ctx_hi, *ctx_lo, *h2_hi, *h2_lo, *ff_hi, *ff_lo;
    cudaGetSymbolAddress((void**)&h_hi,   g_h_hi);
    cudaGetSymbolAddress((void**)&h_lo,   g_h_lo);
    cudaGetSymbolAddress((void**)&q_hi,   g_q_hi);
    cudaGetSymbolAddress((void**)&q_lo,   g_q_lo);
    cudaGetSymbolAddress((void**)&k_hi,   g_k_hi);
    cudaGetSymbolAddress((void**)&k_lo,   g_k_lo);
    cudaGetSymbolAddress((void**)&v_hi,   g_v_hi);
    cudaGetSymbolAddress((void**)&v_lo,   g_v_lo);
    cudaGetSymbolAddress((void**)&ctx_hi, g_ctx_hi);
    cudaGetSymbolAddress((void**)&ctx_lo, g_ctx_lo);
    cudaGetSymbolAddress((void**)&h2_hi,  g_h2_hi);
    cudaGetSymbolAddress((void**)&h2_lo,  g_h2_lo);
    cudaGetSymbolAddress((void**)&ff_hi,  g_ff_hi);
    cudaGetSymbolAddress((void**)&ff_lo,  g_ff_lo);
    __half *wq_hi, *wq_lo, *wk_hi, *wk_lo, *wv_hi, *wv_lo;
    __half *wo_hi, *wo_lo, *w1_hi, *w1_lo, *w2_hi, *w2_lo;
    cudaGetSymbolAddress((void**)&wq_hi, g_wq_hi);
    cudaGetSymbolAddress((void**)&wq_lo, g_wq_lo);
    cudaGetSymbolAddress((void**)&wk_hi, g_wk_hi);
    cudaGetSymbolAddress((void**)&wk_lo, g_wk_lo);
    cudaGetSymbolAddress((void**)&wv_hi, g_wv_hi);
    cudaGetSymbolAddress((void**)&wv_lo, g_wv_lo);
    cudaGetSymbolAddress((void**)&wo_hi, g_wo_hi);
    cudaGetSymbolAddress((void**)&wo_lo, g_wo_lo);
    cudaGetSymbolAddress((void**)&w1_hi, g_w1_hi);
    cudaGetSymbolAddress((void**)&w1_lo, g_w1_lo);
    cudaGetSymbolAddress((void**)&w2_hi, g_w2_hi);
    cudaGetSymbolAddress((void**)&w2_lo, g_w2_lo);

    cudaFuncSetAttribute(flash_mma,
                         cudaFuncAttributeMaxDynamicSharedMemorySize, FA_SMEM);
    cudaFuncSetAttribute(gemm_tc<EPI_SPLIT>,
                         cudaFuncAttributeMaxDynamicSharedMemorySize, GEMM_SMEM);
    cudaFuncSetAttribute(gemm_tc<EPI_BIAS_RES>,
                         cudaFuncAttributeMaxDynamicSharedMemorySize, GEMM_SMEM);
    cudaFuncSetAttribute(gemm_tc<EPI_BIAS_GELU>,
                         cudaFuncAttributeMaxDynamicSharedMemorySize, GEMM_SMEM);

    /* 0) convert all weights to fp16 hi/lo */
    cvt6_kernel<<<12288, 256>>>(wq, wk, wv, wo, w1, w2,
                                wq_hi, wq_lo, wk_hi, wk_lo, wv_hi, wv_lo,
                                wo_hi, wo_lo, w1_hi, w1_lo, w2_hi, w2_lo);

    /* 1) h = LN(x) (hi/lo fp16) */
    ln_kernel<<<NROWS, 256>>>(x, a1, s1, h_hi, h_lo);

    /* 2) q/k/v = h @ W{q,k,v} -> fp16 hi/lo */
    dim3 g_dd(D_MODEL / BN, NROWS / BM);
    gemm_tc<EPI_SPLIT><<<g_dd, TC_THREADS, GEMM_SMEM>>>(
        h_hi, h_lo, wq_hi, wq_lo, nullptr, nullptr, nullptr, q_hi, q_lo,
        NROWS, D_MODEL, D_MODEL);
    gemm_tc<EPI_SPLIT><<<g_dd, TC_THREADS, GEMM_SMEM>>>(
        h_hi, h_lo, wk_hi, wk_lo, nullptr, nullptr, nullptr, k_hi, k_lo,
        NROWS, D_MODEL, D_MODEL);
    gemm_tc<EPI_SPLIT><<<g_dd, TC_THREADS, GEMM_SMEM>>>(
        h_hi, h_lo, wv_hi, wv_lo, nullptr, nullptr, nullptr, v_hi, v_lo,
        NROWS, D_MODEL, D_MODEL);

    /* 3) causal flash attention (tensor cores) -> ctx hi/lo */
    flash_mma<<<dim3(SEQ / 128, NHEAD, BATCH), 256, FA_SMEM>>>(
        q_hi, q_lo, k_hi, k_lo, v_hi, v_lo, ctx_hi, ctx_lo);

    /* 4) x2 = x + ctx @ wo + bo (fp32) */
    gemm_tc<EPI_BIAS_RES><<<g_dd, TC_THREADS, GEMM_SMEM>>>(
        ctx_hi, ctx_lo, wo_hi, wo_lo, bo, x, x2, nullptr, nullptr,
        NROWS, D_MODEL, D_MODEL);

    /* 5) h2 = LN(x2) (hi/lo fp16) */
    ln_kernel<<<NROWS, 256>>>(x2, a2, s2, h2_hi, h2_lo);

    /* 6) ff = gelu(h2 @ w1 + b1) (hi/lo fp16) */
    gemm_tc<EPI_BIAS_GELU><<<dim3(FFDIM / BN, NROWS / BM), TC_THREADS, GEMM_SMEM>>>(
        h2_hi, h2_lo, w1_hi, w1_lo, b1, nullptr, nullptr, ff_hi, ff_lo,
        NROWS, FFDIM, D_MODEL);

    /* 7) out = x2 + ff @ w2 + b2 (fp32) */
    gemm_tc<EPI_BIAS_RES><<<g_dd, TC_THREADS, GEMM_SMEM>>>(
        ff_hi, ff_lo, w2_hi, w2_lo, b2, x2, out, nullptr, nullptr,
        NROWS, D_MODEL, FFDIM);
}